// round 5
// baseline (speedup 1.0000x reference)
#include <cuda_runtime.h>
#include <cstdint>
#include <cstddef>

#define BATCH   4096
#define FFI     64
#define DDIM    256
#define PAIRS   2016
#define THREADS 128
#define KC      64            // K elements per chunk
#define NCH     (DDIM / KC)   // 4
#define SROW    68            // padded smem row stride (words)
#define OROW    67            // epilogue staging row stride (words)

// per-warp tiles: 20 upper-triangular m16n8 tiles, 5 per warp.
// cTMI/cTNJ: tile (m-strip, n-tile). cMASK: union of 8-row groups a warp
// must load per ks (A strips use groups {2mi,2mi+1}, B tiles group {nj};
// B frags alias A raw words since both operands are the same matrix).
__device__ constexpr int cTMI[4][5] = {{0,0,0,0,0},{0,0,0,1,1},{1,1,1,1,2},{2,2,2,3,3}};
__device__ constexpr int cTNJ[4][5] = {{0,1,2,3,4},{5,6,7,2,3},{4,5,6,7,4},{5,6,7,6,7}};
__device__ constexpr unsigned cMASK[4] = {0x1Fu, 0xEFu, 0xFCu, 0xF0u};

__device__ __forceinline__ uint32_t f2tf32(float x) {
    uint32_t r;
    asm("cvt.rna.tf32.f32 %0, %1;" : "=r"(r) : "f"(x));
    return r;
}

__device__ __forceinline__ void mma8(float& d0, float& d1, float& d2, float& d3,
                                     uint32_t a0, uint32_t a1, uint32_t a2, uint32_t a3,
                                     uint32_t b0, uint32_t b1) {
    asm("mma.sync.aligned.m16n8k8.row.col.f32.tf32.tf32.f32 "
        "{%0,%1,%2,%3}, {%4,%5,%6,%7}, {%8,%9}, {%0,%1,%2,%3};"
        : "+f"(d0), "+f"(d1), "+f"(d2), "+f"(d3)
        : "r"(a0), "r"(a1), "r"(a2), "r"(a3), "r"(b0), "r"(b1));
}

template <int W>
__device__ __forceinline__ void chunk_mma(const uint32_t* __restrict__ sb,
                                          int lid, float (&acc)[20]) {
    const int grp = lid >> 2, quad = lid & 3;
    const uint32_t* base = sb + grp * SROW + quad;
#pragma unroll
    for (int ks = 0; ks < KC / 8; ks++) {
        const int k = ks * 8;
        // raw tf32 words: c[g][0] = row(8g+grp,k+quad), c[g][1] = k+quad+4
        uint32_t c[8][2];
#pragma unroll
        for (int g = 0; g < 8; g++) {
            if (cMASK[W] & (1u << g)) {
                c[g][0] = base[g * 8 * SROW + k];
                c[g][1] = base[g * 8 * SROW + k + 4];
            }
        }
#pragma unroll
        for (int t = 0; t < 5; t++) {
            const int mi = cTMI[W][t];
            const int nj = cTNJ[W][t];
            // A frag from groups {2mi, 2mi+1}; B frag aliases group {nj}
            mma8(acc[4 * t], acc[4 * t + 1], acc[4 * t + 2], acc[4 * t + 3],
                 c[2 * mi][0], c[2 * mi + 1][0], c[2 * mi][1], c[2 * mi + 1][1],
                 c[nj][0], c[nj][1]);
        }
    }
}

template <int W>
__device__ __forceinline__ void stage_out(const float (&acc)[20], int lid,
                                          float* __restrict__ sout) {
    const int grp = lid >> 2, quad = lid & 3;
#pragma unroll
    for (int t = 0; t < 5; t++) {
        const int mi = cTMI[W][t];
        const int nj = cTNJ[W][t];
        const int i0 = mi * 16 + grp, i1 = i0 + 8;
        const int j0 = nj * 8 + 2 * quad, j1 = j0 + 1;
        // tiles are disjoint (i,j) regions; j<=i cells are never read back
        sout[i0 * OROW + j0] = acc[4 * t + 0];
        sout[i0 * OROW + j1] = acc[4 * t + 1];
        sout[i1 * OROW + j0] = acc[4 * t + 2];
        sout[i1 * OROW + j1] = acc[4 * t + 3];
    }
}

__global__ void __launch_bounds__(THREADS, 1)
gram_mma_kernel(const float* __restrict__ in, float* __restrict__ out) {
    __shared__ __align__(16) uint32_t sb[2][FFI * SROW];   // 34816 B

    const int tid = threadIdx.x;
    const int wid = tid >> 5, lid = tid & 31;
    const int b = blockIdx.x;

    const float4* src = reinterpret_cast<const float4*>(in)
                        + (size_t)b * FFI * (DDIM / 4);
    const int lrow = tid >> 4;      // 0..7 row-within-group-of-8
    const int lcol = tid & 15;      // float4 column within chunk

    float4 regs[8];
    auto load_chunk = [&](int c) {
#pragma unroll
        for (int i = 0; i < 8; i++) {
            const int r = i * 8 + lrow;
            regs[i] = __ldg(src + (size_t)r * (DDIM / 4) + c * (KC / 4) + lcol);
        }
    };
    auto store_chunk = [&](int buf) {
#pragma unroll
        for (int i = 0; i < 8; i++) {
            const int r = i * 8 + lrow;
            uint4 v;
            v.x = f2tf32(regs[i].x); v.y = f2tf32(regs[i].y);
            v.z = f2tf32(regs[i].z); v.w = f2tf32(regs[i].w);
            *reinterpret_cast<uint4*>(&sb[buf][r * SROW + lcol * 4]) = v;
        }
    };

    float acc[20];
#pragma unroll
    for (int i = 0; i < 20; i++) acc[i] = 0.0f;

    load_chunk(0);
    for (int c = 0; c < NCH; c++) {
        store_chunk(c & 1);
        __syncthreads();
        if (c + 1 < NCH) load_chunk(c + 1);
        const uint32_t* buf = sb[c & 1];
        switch (wid) {
            case 0:  chunk_mma<0>(buf, lid, acc); break;
            case 1:  chunk_mma<1>(buf, lid, acc); break;
            case 2:  chunk_mma<2>(buf, lid, acc); break;
            default: chunk_mma<3>(buf, lid, acc); break;
        }
        __syncthreads();   // orders buffer reuse two iterations apart
    }

    // ---- epilogue: stage in smem (union with dead tile buffers), then
    // fully coalesced global stores ----
    float* sout = reinterpret_cast<float*>(sb);      // [64][OROW]
    switch (wid) {
        case 0:  stage_out<0>(acc, lid, sout); break;
        case 1:  stage_out<1>(acc, lid, sout); break;
        case 2:  stage_out<2>(acc, lid, sout); break;
        default: stage_out<3>(acc, lid, sout); break;
    }
    __syncthreads();

    float* ob = out + (size_t)b * PAIRS;
    // linear index p -> (i,j), base(i) = 63i - i(i-1)/2
#pragma unroll 1
    for (int p = tid; p < PAIRS; p += THREADS) {
        int i = (int)((127.0f - sqrtf(16129.0f - 8.0f * (float)p)) * 0.5f);
        if (i < 0) i = 0;
        if (i > 62) i = 62;
        while (63 * (i + 1) - ((i + 1) * i) / 2 <= p) i++;
        while (63 * i - (i * (i - 1)) / 2 > p) i--;
        const int j = p - (63 * i - (i * (i - 1)) / 2) + i + 1;
        ob[p] = sout[i * OROW + j];
    }
}

extern "C" void kernel_launch(void* const* d_in, const int* in_sizes, int n_in,
                              void* d_out, int out_size) {
    const float* in = (const float*)d_in[0];
    float* out = (float*)d_out;
    (void)in_sizes; (void)n_in; (void)out_size;
    gram_mma_kernel<<<BATCH, THREADS>>>(in, out);
}

// round 6
// speedup vs baseline: 1.2930x; 1.2930x over previous
#include <cuda_runtime.h>
#include <cstdint>
#include <cstddef>

#define BATCH   4096
#define FFI     64
#define DDIM    256
#define PAIRS   2016
#define THREADS 128
#define KC      64            // K elements per chunk
#define NCH     (DDIM / KC)   // 4
#define SROW    68            // padded smem row stride (words)

// per-warp tiles: 20 upper-triangular m16n8 tiles, 5 per warp.
// cTMI/cTNJ: tile (m-strip, n-tile). cMASK: union of 8-row groups a warp
// must load per ks (A strips use groups {2mi,2mi+1}, B tiles group {nj};
// B frags alias A raw words since both operands are the same matrix).
__device__ constexpr int cTMI[4][5] = {{0,0,0,0,0},{0,0,0,1,1},{1,1,1,1,2},{2,2,2,3,3}};
__device__ constexpr int cTNJ[4][5] = {{0,1,2,3,4},{5,6,7,2,3},{4,5,6,7,4},{5,6,7,6,7}};
__device__ constexpr unsigned cMASK[4] = {0x1Fu, 0xEFu, 0xFCu, 0xF0u};

__device__ __forceinline__ uint32_t f2tf32(float x) {
    uint32_t r;
    asm("cvt.rna.tf32.f32 %0, %1;" : "=r"(r) : "f"(x));
    return r;
}

__device__ __forceinline__ void mma8(float& d0, float& d1, float& d2, float& d3,
                                     uint32_t a0, uint32_t a1, uint32_t a2, uint32_t a3,
                                     uint32_t b0, uint32_t b1) {
    asm("mma.sync.aligned.m16n8k8.row.col.f32.tf32.tf32.f32 "
        "{%0,%1,%2,%3}, {%4,%5,%6,%7}, {%8,%9}, {%0,%1,%2,%3};"
        : "+f"(d0), "+f"(d1), "+f"(d2), "+f"(d3)
        : "r"(a0), "r"(a1), "r"(a2), "r"(a3), "r"(b0), "r"(b1));
}

template <int W>
__device__ __forceinline__ void chunk_mma(const uint32_t* __restrict__ sb,
                                          int lid, float (&acc)[20]) {
    const int grp = lid >> 2, quad = lid & 3;
    const uint32_t* base = sb + grp * SROW + quad;
#pragma unroll
    for (int ks = 0; ks < KC / 8; ks++) {
        const int k = ks * 8;
        // raw tf32 words: c[g][0] = row(8g+grp, k+quad), c[g][1] = k+quad+4
        uint32_t c[8][2];
#pragma unroll
        for (int g = 0; g < 8; g++) {
            if (cMASK[W] & (1u << g)) {
                c[g][0] = base[g * 8 * SROW + k];
                c[g][1] = base[g * 8 * SROW + k + 4];
            }
        }
#pragma unroll
        for (int t = 0; t < 5; t++) {
            const int mi = cTMI[W][t];
            const int nj = cTNJ[W][t];
            // A frag from groups {2mi, 2mi+1}; B frag aliases group {nj}
            mma8(acc[4 * t], acc[4 * t + 1], acc[4 * t + 2], acc[4 * t + 3],
                 c[2 * mi][0], c[2 * mi + 1][0], c[2 * mi][1], c[2 * mi + 1][1],
                 c[nj][0], c[nj][1]);
        }
    }
}

__device__ __forceinline__ void stp(float* __restrict__ ob, int i, int j,
                                    float v, bool need_check) {
    if (!need_check || j > i)
        ob[i * FFI - (i * (i + 1)) / 2 + j - i - 1] = v;
}

template <int W>
__device__ __forceinline__ void epilogue(const float (&acc)[20], int lid,
                                         float* __restrict__ ob) {
    const int grp = lid >> 2, quad = lid & 3;
#pragma unroll
    for (int t = 0; t < 5; t++) {
        const int mi = cTMI[W][t];
        const int nj = cTNJ[W][t];
        const bool chk = (nj < 2 * mi + 2);   // tile straddles the diagonal
        const int i0 = mi * 16 + grp, i1 = i0 + 8;
        const int j0 = nj * 8 + 2 * quad, j1 = j0 + 1;
        stp(ob, i0, j0, acc[4 * t + 0], chk);
        stp(ob, i0, j1, acc[4 * t + 1], chk);
        stp(ob, i1, j0, acc[4 * t + 2], chk);
        stp(ob, i1, j1, acc[4 * t + 3], chk);
    }
}

__global__ void __launch_bounds__(THREADS, 5)
gram_mma_kernel(const float* __restrict__ in, float* __restrict__ out) {
    __shared__ __align__(16) uint32_t sb[2][FFI * SROW];   // 34816 B

    const int tid = threadIdx.x;
    const int wid = tid >> 5, lid = tid & 31;
    const int b = blockIdx.x;

    const float4* src = reinterpret_cast<const float4*>(in)
                        + (size_t)b * FFI * (DDIM / 4);
    const int lrow = tid >> 4;      // 0..7 row-within-group-of-8
    const int lcol = tid & 15;      // float4 column within chunk

    float4 regs[8];
    auto load_chunk = [&](int c) {
#pragma unroll
        for (int i = 0; i < 8; i++) {
            const int r = i * 8 + lrow;
            regs[i] = __ldg(src + (size_t)r * (DDIM / 4) + c * (KC / 4) + lcol);
        }
    };
    auto store_chunk = [&](int buf) {
#pragma unroll
        for (int i = 0; i < 8; i++) {
            const int r = i * 8 + lrow;
            uint4 v;
            v.x = f2tf32(regs[i].x); v.y = f2tf32(regs[i].y);
            v.z = f2tf32(regs[i].z); v.w = f2tf32(regs[i].w);
            *reinterpret_cast<uint4*>(&sb[buf][r * SROW + lcol * 4]) = v;
        }
    };

    float acc[20];
#pragma unroll
    for (int i = 0; i < 20; i++) acc[i] = 0.0f;

    load_chunk(0);
    for (int c = 0; c < NCH; c++) {
        store_chunk(c & 1);
        __syncthreads();
        if (c + 1 < NCH) load_chunk(c + 1);
        const uint32_t* buf = sb[c & 1];
        switch (wid) {
            case 0:  chunk_mma<0>(buf, lid, acc); break;
            case 1:  chunk_mma<1>(buf, lid, acc); break;
            case 2:  chunk_mma<2>(buf, lid, acc); break;
            default: chunk_mma<3>(buf, lid, acc); break;
        }
        __syncthreads();   // orders buffer reuse two iterations apart
    }

    float* ob = out + (size_t)b * PAIRS;
    switch (wid) {
        case 0:  epilogue<0>(acc, lid, ob); break;
        case 1:  epilogue<1>(acc, lid, ob); break;
        case 2:  epilogue<2>(acc, lid, ob); break;
        default: epilogue<3>(acc, lid, ob); break;
    }
}

extern "C" void kernel_launch(void* const* d_in, const int* in_sizes, int n_in,
                              void* d_out, int out_size) {
    const float* in = (const float*)d_in[0];
    float* out = (float*)d_out;
    (void)in_sizes; (void)n_in; (void)out_size;
    gram_mma_kernel<<<BATCH, THREADS>>>(in, out);
}

// round 8
// speedup vs baseline: 1.2982x; 1.0040x over previous
#include <cuda_runtime.h>
#include <cstdint>
#include <cstddef>

#define BATCH   4096
#define FFI     64
#define DDIM    256
#define PAIRS   2016
#define THREADS 128
#define KC      64            // K elements per chunk
#define NCH     (DDIM / KC)   // 4
#define SROW    72            // padded smem row stride (words), ==8 mod 32

// per-warp tiles: 20 upper-triangular m16n8 tiles, 5 per warp.
// cTMI/cTNJ: tile (m-strip, n-tile). cMASK: union of 8-row groups a warp
// must touch per ks (A strips use groups {2mi,2mi+1}, B tiles group {nj};
// B frags alias A raw words since both operands are the same matrix).
__device__ constexpr int cTMI[4][5] = {{0,0,0,0,0},{0,0,0,1,1},{1,1,1,1,2},{2,2,2,3,3}};
__device__ constexpr int cTNJ[4][5] = {{0,1,2,3,4},{5,6,7,2,3},{4,5,6,7,4},{5,6,7,6,7}};
__device__ constexpr unsigned cMASK[4] = {0x1Fu, 0xEFu, 0xFCu, 0xF0u};

__device__ __forceinline__ uint32_t f2tf32(float x) {
    uint32_t r;
    asm("cvt.rna.tf32.f32 %0, %1;" : "=r"(r) : "f"(x));
    return r;
}

__device__ __forceinline__ void mma8(float& d0, float& d1, float& d2, float& d3,
                                     uint32_t a0, uint32_t a1, uint32_t a2, uint32_t a3,
                                     uint32_t b0, uint32_t b1) {
    asm("mma.sync.aligned.m16n8k8.row.col.f32.tf32.tf32.f32 "
        "{%0,%1,%2,%3}, {%4,%5,%6,%7}, {%8,%9}, {%0,%1,%2,%3};"
        : "+f"(d0), "+f"(d1), "+f"(d2), "+f"(d3)
        : "r"(a0), "r"(a1), "r"(a2), "r"(a3), "r"(b0), "r"(b1));
}

// k-permutation trick: the mma's canonical lane k-slots are (quad, quad+4),
// but since C = A*A^T uses the SAME smem words for A and B fragments with the
// SAME lane mapping, any k-permutation applied identically to both operands
// leaves the accumulated result unchanged. We use slots (2*quad, 2*quad+1),
// which is a single conflict-free LDS.64 per 8-row group.
template <int W>
__device__ __forceinline__ void chunk_mma(const uint32_t* __restrict__ sb,
                                          int lid, float (&acc)[20]) {
    const int grp = lid >> 2, quad = lid & 3;
    const uint32_t* base = sb + grp * SROW + 2 * quad;
#pragma unroll
    for (int ks = 0; ks < KC / 8; ks++) {
        const int k = ks * 8;
        // c[g][0] = row(8g+grp), col k+2q ; c[g][1] = col k+2q+1
        uint32_t c[8][2];
#pragma unroll
        for (int g = 0; g < 8; g++) {
            if (cMASK[W] & (1u << g)) {
                uint2 v = *reinterpret_cast<const uint2*>(base + g * 8 * SROW + k);
                c[g][0] = v.x; c[g][1] = v.y;
            }
        }
#pragma unroll
        for (int t = 0; t < 5; t++) {
            const int mi = cTMI[W][t];
            const int nj = cTNJ[W][t];
            // A frag from groups {2mi, 2mi+1}; B frag aliases group {nj}
            mma8(acc[4 * t], acc[4 * t + 1], acc[4 * t + 2], acc[4 * t + 3],
                 c[2 * mi][0], c[2 * mi + 1][0], c[2 * mi][1], c[2 * mi + 1][1],
                 c[nj][0], c[nj][1]);
        }
    }
}

__device__ __forceinline__ void stp(float* __restrict__ ob, int i, int j,
                                    float v, bool need_check) {
    if (!need_check || j > i)
        ob[i * FFI - (i * (i + 1)) / 2 + j - i - 1] = v;
}

template <int W>
__device__ __forceinline__ void epilogue(const float (&acc)[20], int lid,
                                         float* __restrict__ ob) {
    const int grp = lid >> 2, quad = lid & 3;
#pragma unroll
    for (int t = 0; t < 5; t++) {
        const int mi = cTMI[W][t];
        const int nj = cTNJ[W][t];
        const bool chk = (nj < 2 * mi + 2);   // tile straddles the diagonal
        const int i0 = mi * 16 + grp, i1 = i0 + 8;
        const int j0 = nj * 8 + 2 * quad, j1 = j0 + 1;
        stp(ob, i0, j0, acc[4 * t + 0], chk);
        stp(ob, i0, j1, acc[4 * t + 1], chk);
        stp(ob, i1, j0, acc[4 * t + 2], chk);
        stp(ob, i1, j1, acc[4 * t + 3], chk);
    }
}

__global__ void __launch_bounds__(THREADS, 5)
gram_mma_kernel(const float* __restrict__ in, float* __restrict__ out) {
    __shared__ __align__(16) uint32_t sb[2][FFI * SROW];   // 36864 B

    const int tid = threadIdx.x;
    const int wid = tid >> 5, lid = tid & 31;
    const int b = blockIdx.x;

    const float4* src = reinterpret_cast<const float4*>(in)
                        + (size_t)b * FFI * (DDIM / 4);
    const int lrow = tid >> 4;      // 0..7 row-within-group-of-8
    const int lcol = tid & 15;      // float4 column within chunk

    float4 regs[8];
    auto load_chunk = [&](int c) {
#pragma unroll
        for (int i = 0; i < 8; i++) {
            const int r = i * 8 + lrow;
            regs[i] = __ldg(src + (size_t)r * (DDIM / 4) + c * (KC / 4) + lcol);
        }
    };
    auto store_chunk = [&](int buf) {
#pragma unroll
        for (int i = 0; i < 8; i++) {
            const int r = i * 8 + lrow;
            uint4 v;
            v.x = f2tf32(regs[i].x); v.y = f2tf32(regs[i].y);
            v.z = f2tf32(regs[i].z); v.w = f2tf32(regs[i].w);
            *reinterpret_cast<uint4*>(&sb[buf][r * SROW + lcol * 4]) = v;
        }
    };

    float acc[20];
#pragma unroll
    for (int i = 0; i < 20; i++) acc[i] = 0.0f;

    // single barrier per chunk: a warp passing sync(c) implies all warps
    // finished mma(c-1), so the same-buffer store two iterations later is safe.
    load_chunk(0);
    for (int c = 0; c < NCH; c++) {
        store_chunk(c & 1);
        __syncthreads();
        if (c + 1 < NCH) load_chunk(c + 1);
        const uint32_t* buf = sb[c & 1];
        switch (wid) {
            case 0:  chunk_mma<0>(buf, lid, acc); break;
            case 1:  chunk_mma<1>(buf, lid, acc); break;
            case 2:  chunk_mma<2>(buf, lid, acc); break;
            default: chunk_mma<3>(buf, lid, acc); break;
        }
    }

    float* ob = out + (size_t)b * PAIRS;
    switch (wid) {
        case 0:  epilogue<0>(acc, lid, ob); break;
        case 1:  epilogue<1>(acc, lid, ob); break;
        case 2:  epilogue<2>(acc, lid, ob); break;
        default: epilogue<3>(acc, lid, ob); break;
    }
}

extern "C" void kernel_launch(void* const* d_in, const int* in_sizes, int n_in,
                              void* d_out, int out_size) {
    const float* in = (const float*)d_in[0];
    float* out = (float*)d_out;
    (void)in_sizes; (void)n_in; (void)out_size;
    gram_mma_kernel<<<BATCH, THREADS>>>(in, out);
}